// round 1
// baseline (speedup 1.0000x reference)
#include <cuda_runtime.h>

#define T_STEPS 28
#define HID 128
#define IND 28
#define NCLS 10
#define BATCH 8192
#define RPB 32   // batch rows per block

// 112 MB scratch for precomputed layer-0 input GEMM (+ fused biases)
__device__ float g_xw0[BATCH * T_STEPS * HID];

__device__ __forceinline__ float ftanh(float x) {
    // tanh(x) = 1 - 2/(e^{2x}+1); saturates correctly at +/-inf, no NaN.
    float e = __expf(2.0f * x);
    return 1.0f - __fdividef(2.0f, e + 1.0f);
}

// ---------------------------------------------------------------------------
// Kernel 1: xw0[b,t,:] = x[b,t,:] @ W_ih0^T + (b_ih0 + b_hh0)
// rows = BATCH*T_STEPS flattened; 32 rows/block, 256 threads, 4x4 thread tile.
// ---------------------------------------------------------------------------
__global__ __launch_bounds__(256, 1) void input_gemm_kernel(
    const float* __restrict__ x, const float* __restrict__ Wih0,
    const float* __restrict__ bih0, const float* __restrict__ bhh0)
{
    __shared__ float Wt[IND * HID];   // W_ih0 transposed: Wt[d][j]
    __shared__ float xs[RPB * IND];
    __shared__ float bs[HID];

    const int tid = threadIdx.x;
    const int r0 = blockIdx.x * RPB;

    for (int idx = tid; idx < HID * IND; idx += 256) {
        int j = idx / IND, d = idx - j * IND;
        Wt[d * HID + j] = Wih0[idx];
    }
    if (tid < HID) bs[tid] = bih0[tid] + bhh0[tid];
    for (int idx = tid; idx < RPB * IND; idx += 256)
        xs[idx] = x[r0 * IND + idx];          // rows are contiguous in x
    __syncthreads();

    const int w = tid >> 5, lane = tid & 31;
    const int rl = 4 * w;      // local rows rl..rl+3
    const int col = 4 * lane;  // cols col..col+3

    const float4 bv = *(const float4*)&bs[col];
    float4 acc[4];
#pragma unroll
    for (int i = 0; i < 4; i++) acc[i] = bv;

#pragma unroll
    for (int d = 0; d < IND; d++) {
        float4 wv = *(const float4*)&Wt[d * HID + col];
#pragma unroll
        for (int i = 0; i < 4; i++) {
            float xv = xs[(rl + i) * IND + d];
            acc[i].x += xv * wv.x; acc[i].y += xv * wv.y;
            acc[i].z += xv * wv.z; acc[i].w += xv * wv.w;
        }
    }
#pragma unroll
    for (int i = 0; i < 4; i++)
        *(float4*)&g_xw0[(r0 + rl + i) * HID + col] = acc[i];
}

// ---------------------------------------------------------------------------
// Kernel 2: fused 2-layer recurrence + FC head.
// One CTA owns 32 batch rows for all 28 steps; all recurrent weights live
// transposed in shared memory (192 KB). No inter-CTA communication.
// ---------------------------------------------------------------------------
__global__ __launch_bounds__(256, 1) void rnn_main_kernel(
    const float* __restrict__ Whh0, const float* __restrict__ Wih1,
    const float* __restrict__ Whh1, const float* __restrict__ bih1,
    const float* __restrict__ bhh1, const float* __restrict__ fcw,
    const float* __restrict__ fcb, float* __restrict__ out)
{
    extern __shared__ float sm[];
    float* Whh0t = sm;             // [k][j] 128x128
    float* Wih1t = sm + 16384;
    float* Whh1t = sm + 32768;
    float* h0s   = sm + 49152;     // [32][128]
    float* h1s   = sm + 53248;     // [32][128]
    float* b1s   = sm + 57344;     // [128]
    // total: 57472 floats = 229,888 B (< 232,448 B limit)

    const int tid = threadIdx.x;
    const int b0 = blockIdx.x * RPB;

    for (int idx = tid; idx < HID * HID; idx += 256) {
        int j = idx >> 7, k = idx & 127;
        Whh0t[k * HID + j] = Whh0[idx];
        Wih1t[k * HID + j] = Wih1[idx];
        Whh1t[k * HID + j] = Whh1[idx];
    }
    for (int idx = tid; idx < RPB * HID; idx += 256) {
        h0s[idx] = 0.0f; h1s[idx] = 0.0f;
    }
    if (tid < HID) b1s[tid] = bih1[tid] + bhh1[tid];
    __syncthreads();

    const int w = tid >> 5, lane = tid & 31;
    const int rl = 4 * w;      // local rows
    const int col = 4 * lane;  // hidden cols

    const float4 b1v = *(const float4*)&b1s[col];

    // prefetch xw0 for t=0
    float4 xp[4];
#pragma unroll
    for (int i = 0; i < 4; i++)
        xp[i] = *(const float4*)&g_xw0[((b0 + rl + i) * T_STEPS + 0) * HID + col];

    for (int t = 0; t < T_STEPS; t++) {
        float4 acc[4];
#pragma unroll
        for (int i = 0; i < 4; i++) acc[i] = xp[i];

        if (t + 1 < T_STEPS) {   // prefetch next step's input-GEMM slice
#pragma unroll
            for (int i = 0; i < 4; i++)
                xp[i] = *(const float4*)&g_xw0[((b0 + rl + i) * T_STEPS + (t + 1)) * HID + col];
        }

        // ---- layer 0 recurrence: acc += h0 @ Whh0^T ----
#pragma unroll 8
        for (int k = 0; k < HID; k++) {
            float4 wv = *(const float4*)&Whh0t[k * HID + col];
#pragma unroll
            for (int i = 0; i < 4; i++) {
                float hv = h0s[(rl + i) * HID + k];
                acc[i].x += hv * wv.x; acc[i].y += hv * wv.y;
                acc[i].z += hv * wv.z; acc[i].w += hv * wv.w;
            }
        }
#pragma unroll
        for (int i = 0; i < 4; i++) {
            acc[i].x = ftanh(acc[i].x); acc[i].y = ftanh(acc[i].y);
            acc[i].z = ftanh(acc[i].z); acc[i].w = ftanh(acc[i].w);
        }
        __syncthreads();   // everyone done reading old h0
#pragma unroll
        for (int i = 0; i < 4; i++)
            *(float4*)&h0s[(rl + i) * HID + col] = acc[i];
        __syncthreads();   // new h0 visible

        // ---- layer 1: acc = b1 + h0_new @ Wih1^T + h1 @ Whh1^T ----
#pragma unroll
        for (int i = 0; i < 4; i++) acc[i] = b1v;
#pragma unroll 4
        for (int k = 0; k < HID; k++) {
            float4 w1 = *(const float4*)&Wih1t[k * HID + col];
            float4 w2 = *(const float4*)&Whh1t[k * HID + col];
#pragma unroll
            for (int i = 0; i < 4; i++) {
                float a = h0s[(rl + i) * HID + k];
                float b = h1s[(rl + i) * HID + k];
                acc[i].x += a * w1.x + b * w2.x;
                acc[i].y += a * w1.y + b * w2.y;
                acc[i].z += a * w1.z + b * w2.z;
                acc[i].w += a * w1.w + b * w2.w;
            }
        }
#pragma unroll
        for (int i = 0; i < 4; i++) {
            acc[i].x = ftanh(acc[i].x); acc[i].y = ftanh(acc[i].y);
            acc[i].z = ftanh(acc[i].z); acc[i].w = ftanh(acc[i].w);
        }
        __syncthreads();   // everyone done reading old h1
#pragma unroll
        for (int i = 0; i < 4; i++)
            *(float4*)&h1s[(rl + i) * HID + col] = acc[i];
        __syncthreads();
    }

    // ---- FC head: out = h1 @ fc_w^T + fc_b (stage fc_w in freed h0s) ----
    for (int idx = tid; idx < NCLS * HID; idx += 256) h0s[idx] = fcw[idx];
    if (tid < NCLS) b1s[tid] = fcb[tid];
    __syncthreads();

    for (int idx = tid; idx < RPB * NCLS; idx += 256) {
        int m = idx / NCLS, c = idx - m * NCLS;
        float a = b1s[c];
#pragma unroll 8
        for (int k = 0; k < HID; k++)
            a += h1s[m * HID + k] * h0s[c * HID + k];
        out[(b0 + m) * NCLS + c] = a;
    }
}

// ---------------------------------------------------------------------------
extern "C" void kernel_launch(void* const* d_in, const int* in_sizes, int n_in,
                              void* d_out, int out_size) {
    const float* x    = (const float*)d_in[0];
    const float* Wih0 = (const float*)d_in[1];
    const float* Whh0 = (const float*)d_in[2];
    const float* bih0 = (const float*)d_in[3];
    const float* bhh0 = (const float*)d_in[4];
    const float* Wih1 = (const float*)d_in[5];
    const float* Whh1 = (const float*)d_in[6];
    const float* bih1 = (const float*)d_in[7];
    const float* bhh1 = (const float*)d_in[8];
    const float* fcw  = (const float*)d_in[9];
    const float* fcb  = (const float*)d_in[10];
    float* out = (float*)d_out;

    cudaFuncSetAttribute(rnn_main_kernel,
                         cudaFuncAttributeMaxDynamicSharedMemorySize, 229888);

    input_gemm_kernel<<<(BATCH * T_STEPS) / RPB, 256>>>(x, Wih0, bih0, bhh0);
    rnn_main_kernel<<<BATCH / RPB, 256, 229888>>>(Whh0, Wih1, Whh1,
                                                  bih1, bhh1, fcw, fcb, out);
}